// round 5
// baseline (speedup 1.0000x reference)
#include <cuda_runtime.h>
#include <cuda_fp16.h>
#include <cstdint>

// Vanilla tanh RNN: h_t = tanh(x_t W_ih^T + b_ih + h_{t-1} W_hh^T + b_hh)
// B=4096, T=256, I=H=64. Output: [hT (B*H) | all h_t (B*T*H)] fp32.
//
// 128 blocks x 128 threads (4 warps = 2 independent PAIRS). A pair owns 16
// batch rows; each warp of the pair owns 32 of the 64 output cols. 1 warp per
// SMSP -> exclusive MUFU/LSU/issue. Per step: h-GEMM (4 independent 4-deep
// fp16 MMA chains) -> tanh -> publish h (STS) -> 64-thread named barrier ->
// tail: out STGs, x-GEMM for t+1, x fp32->fp16 staging, cp.async prefetch.
// x flows through a 3-deep cp.async ring (no register pipeline, no LDG
// scoreboard stalls). Weights are register-resident B-fragments.

constexpr int Bsz = 4096;
constexpr int T   = 256;
constexpr int H   = 64;
constexpr int NBROWS = 32;   // rows per block (2 pairs x 16)
constexpr int NTHREADS = 128;
constexpr int SU  = 36;      // fp16 tile row stride (u32 units)
constexpr int RS  = 68;      // fp32 ring row stride (floats)

__device__ __forceinline__ uint32_t packh2(float a, float b) {
    __half2 h = __floats2half2_rn(a, b);
    return *reinterpret_cast<uint32_t*>(&h);
}

__device__ __forceinline__ void mma16(float* c, const uint32_t* a, const uint32_t* b) {
    asm volatile(
        "mma.sync.aligned.m16n8k16.row.col.f32.f16.f16.f32 "
        "{%0,%1,%2,%3}, {%4,%5,%6,%7}, {%8,%9}, {%0,%1,%2,%3};"
        : "+f"(c[0]), "+f"(c[1]), "+f"(c[2]), "+f"(c[3])
        : "r"(a[0]), "r"(a[1]), "r"(a[2]), "r"(a[3]), "r"(b[0]), "r"(b[1]));
}

__device__ __forceinline__ void ldsm4(uint32_t* a, uint32_t addr) {
    asm volatile("ldmatrix.sync.aligned.m8n8.x4.shared.b16 {%0,%1,%2,%3}, [%4];"
                 : "=r"(a[0]), "=r"(a[1]), "=r"(a[2]), "=r"(a[3])
                 : "r"(addr));
}

__device__ __forceinline__ void cpasync16(uint32_t sdst, const void* gsrc) {
    asm volatile("cp.async.ca.shared.global [%0], [%1], 16;"
                 :: "r"(sdst), "l"(gsrc) : "memory");
}
__device__ __forceinline__ void cpcommit() {
    asm volatile("cp.async.commit_group;" ::: "memory");
}
__device__ __forceinline__ void cpwait1() {
    asm volatile("cp.async.wait_group 1;" ::: "memory");
}

// tanh = 1 - 2/(e^{2z}+1); EX2+RCP, exact saturation at +/-1.
__device__ __forceinline__ float fast_tanh(float z) {
    float e = __expf(2.0f * z);
    return 1.0f - __fdividef(2.0f, e + 1.0f);
}

__global__ void __launch_bounds__(NTHREADS, 1)
rnn_fused(const float* __restrict__ x, const float* __restrict__ h0,
          const float* __restrict__ Wih, const float* __restrict__ Whh,
          const float* __restrict__ bih, const float* __restrict__ bhh,
          float* __restrict__ dout)
{
    __shared__ __align__(16) uint32_t hbuf[2][2][16 * SU];  // [buf][pair]
    __shared__ __align__(16) uint32_t xb16[2][2][16 * SU];  // [buf][pair]
    __shared__ __align__(16) float    ring[3][2][16 * RS];  // [slot][pair]

    const int tid  = threadIdx.x;
    const int warp = tid >> 5;
    const int lane = tid & 31;
    const int gid  = lane >> 2;
    const int tig  = lane & 3;
    const int p    = warp >> 1;      // pair id
    const int q    = warp & 1;       // warp within pair (col half)
    const int b0   = blockIdx.x * NBROWS;
    const int prow0 = b0 + p * 16;   // global batch row base of this pair

    // ---- weight B-fragments (fp16, register resident): 4 n-tiles x 4 kt ----
    uint32_t wih[4][4][2], whh[4][4][2];
    #pragma unroll
    for (int nt = 0; nt < 4; ++nt) {
        const int n = q * 32 + nt * 8 + gid;
        #pragma unroll
        for (int kt = 0; kt < 4; ++kt) {
            const int k = kt * 16 + 2 * tig;
            wih[nt][kt][0] = packh2(Wih[n * H + k],     Wih[n * H + k + 1]);
            wih[nt][kt][1] = packh2(Wih[n * H + k + 8], Wih[n * H + k + 9]);
            whh[nt][kt][0] = packh2(Whh[n * H + k],     Whh[n * H + k + 1]);
            whh[nt][kt][1] = packh2(Whh[n * H + k + 8], Whh[n * H + k + 9]);
        }
    }
    float bias[4][2];
    #pragma unroll
    for (int nt = 0; nt < 4; ++nt) {
        const int col = q * 32 + nt * 8 + 2 * tig;
        bias[nt][0] = bih[col]     + bhh[col];
        bias[nt][1] = bih[col + 1] + bhh[col + 1];
    }

    // ---- smem addresses ----
    const int mat = lane >> 3, mr = lane & 7;
    const uint32_t aoff =                       // ldmatrix lane offset (bytes)
        (uint32_t)(((mat & 1) * 8 + mr) * SU * 4 + (mat >> 1) * 16);
    uint32_t hbB[2], xbB[2];
    hbB[0] = (uint32_t)__cvta_generic_to_shared(&hbuf[0][p][0]) + aoff;
    hbB[1] = (uint32_t)__cvta_generic_to_shared(&hbuf[1][p][0]) + aoff;
    xbB[0] = (uint32_t)__cvta_generic_to_shared(&xb16[0][p][0]) + aoff;
    xbB[1] = (uint32_t)__cvta_generic_to_shared(&xb16[1][p][0]) + aoff;

    // ---- x staging mapping: warp q covers pair-rows q*8..q*8+7 ----
    const int rr  = q * 8 + (lane >> 2);    // pair-local row this lane stages
    const int c0  = lane & 3;               // base chunk (16B = 4 floats)
    const float* xg = x + ((size_t)(prow0 + rr) * T) * H;  // + t*H + chunk*4
    uint32_t rdst[3];
    #pragma unroll
    for (int s = 0; s < 3; ++s)
        rdst[s] = (uint32_t)__cvta_generic_to_shared(&ring[s][p][rr * RS + c0 * 4]);

    // ---- prologue: h0 -> hbuf[0] (both warps of pair cooperate) ----
    {
        const int wl = q * 32 + lane;       // 0..63 within pair
        #pragma unroll
        for (int j = 0; j < 8; ++j) {
            const int u = wl + 64 * j;      // 0..511
            const int r = u >> 5, cu = u & 31;
            const float2 v = *(const float2*)(h0 + (size_t)(prow0 + r) * H + 2 * cu);
            hbuf[0][p][r * SU + cu] = packh2(v.x, v.y);
        }
    }

    // ---- prologue: cp.async x(0),x(1),x(2) into ring slots 0,1,2 ----
    #pragma unroll
    for (int tt = 0; tt < 3; ++tt) {
        #pragma unroll
        for (int j = 0; j < 4; ++j) {
            const int c = c0 + 4 * j;
            cpasync16(rdst[tt] + j * 64, xg + (size_t)tt * H + c * 4);
        }
        cpcommit();                          // groups G0,G1,G2
    }
    cpwait1();                               // G0,G1 done
    // cvt x(0)->xb16[0], x(1)->xb16[1]
    #pragma unroll
    for (int tt = 0; tt < 2; ++tt) {
        #pragma unroll
        for (int j = 0; j < 4; ++j) {
            const int c = c0 + 4 * j;
            const float4 v = *(const float4*)&ring[tt][p][rr * RS + c * 4];
            *(uint2*)&xb16[tt][p][rr * SU + c * 2] =
                make_uint2(packh2(v.x, v.y), packh2(v.z, v.w));
        }
    }
    // issue x(3) -> slot 0 (x(0) consumed)
    #pragma unroll
    for (int j = 0; j < 4; ++j) {
        const int c = c0 + 4 * j;
        cpasync16(rdst[0] + j * 64, xg + (size_t)3 * H + c * 4);
    }
    cpcommit();                              // G3
    __syncthreads();                         // h0 + x0/x1 fp16 visible

    // ---- acc = bias + x(0) @ W_ih^T ----
    float acc[4][4];
    #pragma unroll
    for (int nt = 0; nt < 4; ++nt) {
        acc[nt][0] = bias[nt][0]; acc[nt][1] = bias[nt][1];
        acc[nt][2] = bias[nt][0]; acc[nt][3] = bias[nt][1];
    }
    #pragma unroll
    for (int kt = 0; kt < 4; ++kt) {
        uint32_t a[4];
        ldsm4(a, xbB[0] + kt * 32);
        #pragma unroll
        for (int nt = 0; nt < 4; ++nt) mma16(acc[nt], a, wih[nt][kt]);
    }

    float* __restrict__ outp = dout + (size_t)Bsz * H;   // [hT | out]
    float hval[4][4];
    const int row0 = prow0 + gid;            // global row (and +8)
    const int colb = q * 32 + 2 * tig;       // output col base (+ nt*8)
    const int cub  = q * 16 + tig;           // h publish u32 col base (+ nt*4)
    const int ar0  = gid * SU;               // h publish row offsets
    const int ar1  = ar0 + 8 * SU;

    #pragma unroll 2
    for (int t = 0; t < T; ++t) {
        const int cur = t & 1, nxt = cur ^ 1;

        // ---- critical: h-GEMM (4 independent chains) ----
        #pragma unroll
        for (int kt = 0; kt < 4; ++kt) {
            uint32_t a[4];
            ldsm4(a, hbB[cur] + kt * 32);
            #pragma unroll
            for (int nt = 0; nt < 4; ++nt) mma16(acc[nt], a, whh[nt][kt]);
        }
        // ---- tanh ----
        #pragma unroll
        for (int nt = 0; nt < 4; ++nt) {
            hval[nt][0] = fast_tanh(acc[nt][0]);
            hval[nt][1] = fast_tanh(acc[nt][1]);
            hval[nt][2] = fast_tanh(acc[nt][2]);
            hval[nt][3] = fast_tanh(acc[nt][3]);
        }
        // ---- publish h_t ----
        {
            uint32_t* hw = &hbuf[nxt][p][0];
            #pragma unroll
            for (int nt = 0; nt < 4; ++nt) {
                hw[ar0 + cub + nt * 4] = packh2(hval[nt][0], hval[nt][1]);
                hw[ar1 + cub + nt * 4] = packh2(hval[nt][2], hval[nt][3]);
            }
        }
        asm volatile("bar.sync %0, 64;" :: "r"(1 + p) : "memory");

        // ================= tail (off the recurrence chain) =================
        // out stores for step t
        #pragma unroll
        for (int nt = 0; nt < 4; ++nt) {
            const int col = colb + nt * 8;
            *(float2*)(outp + ((size_t)row0 * T + t) * H + col) =
                make_float2(hval[nt][0], hval[nt][1]);
            *(float2*)(outp + ((size_t)(row0 + 8) * T + t) * H + col) =
                make_float2(hval[nt][2], hval[nt][3]);
        }
        // x-GEMM for t+1: acc = bias + x(t+1) @ W_ih^T
        if (t + 1 < T) {
            #pragma unroll
            for (int nt = 0; nt < 4; ++nt) {
                acc[nt][0] = bias[nt][0]; acc[nt][1] = bias[nt][1];
                acc[nt][2] = bias[nt][0]; acc[nt][3] = bias[nt][1];
            }
            const uint32_t xbase = xbB[nxt & 1];
            #pragma unroll
            for (int kt = 0; kt < 4; ++kt) {
                uint32_t a[4];
                ldsm4(a, xbase + kt * 32);
                #pragma unroll
                for (int nt = 0; nt < 4; ++nt) mma16(acc[nt], a, wih[nt][kt]);
            }
        }
        // stage x(t+2): ring -> fp16 xb16[t&1]
        if (t + 2 < T) {
            cpwait1();                                   // x(t+2) arrived
            const int s = (t + 2) % 3;
            const float* rp = &ring[s][p][rr * RS];
            uint32_t* xw = &xb16[cur][p][rr * SU];
            #pragma unroll
            for (int j = 0; j < 4; ++j) {
                const int c = c0 + 4 * j;
                const float4 v = *(const float4*)(rp + c * 4);
                *(uint2*)(xw + c * 2) =
                    make_uint2(packh2(v.x, v.y), packh2(v.z, v.w));
            }
        }
        // prefetch x(t+4) -> slot (t+1)%3
        {
            const int tf = (t + 4 < T) ? (t + 4) : (T - 1);
            const uint32_t d = rdst[(t + 1) % 3];
            #pragma unroll
            for (int j = 0; j < 4; ++j) {
                const int c = c0 + 4 * j;
                cpasync16(d + j * 64, xg + (size_t)tf * H + c * 4);
            }
            cpcommit();
        }
    }

    // ---- final hidden state hT ----
    #pragma unroll
    for (int nt = 0; nt < 4; ++nt) {
        const int col = colb + nt * 8;
        *(float2*)(dout + (size_t)row0 * H + col) =
            make_float2(hval[nt][0], hval[nt][1]);
        *(float2*)(dout + (size_t)(row0 + 8) * H + col) =
            make_float2(hval[nt][2], hval[nt][3]);
    }
}

extern "C" void kernel_launch(void* const* d_in, const int* in_sizes, int n_in,
                              void* d_out, int out_size) {
    const float* x   = (const float*)d_in[0];
    const float* h0  = (const float*)d_in[1];
    const float* Wih = (const float*)d_in[2];
    const float* Whh = (const float*)d_in[3];
    const float* bih = (const float*)d_in[4];
    const float* bhh = (const float*)d_in[5];
    (void)in_sizes; (void)n_in; (void)out_size;

    rnn_fused<<<Bsz / NBROWS, NTHREADS>>>(x, h0, Wih, Whh, bih, bhh, (float*)d_out);
}